// round 1
// baseline (speedup 1.0000x reference)
#include <cuda_runtime.h>

#define N_NODES 50000
#define N_EDGES 800000
#define N_FEATS 64

// Scratch (allocation-free): ~3.4 MB total
__device__ float g_deg[N_NODES];
__device__ float g_dinv[N_NODES];
__device__ float g_y0[N_NODES];
__device__ float g_t1[N_NODES];
__device__ float g_t2[N_NODES];
__device__ float g_norm[N_EDGES];

// ---------------------------------------------------------------------------
// Kernel 1: deg init (self-loop contributes 1) + projection y0 = x[i,:] . w
// Warp per node: lane l reads feats l and l+32 (fully coalesced 128B rows).
// ---------------------------------------------------------------------------
__global__ void k_proj_init(const float* __restrict__ x,
                            const float* __restrict__ W) {
    int warp = (blockIdx.x * blockDim.x + threadIdx.x) >> 5;
    int lane = threadIdx.x & 31;
    if (warp >= N_NODES) return;
    const float* xr = x + (size_t)warp * N_FEATS;
    float w0 = __ldg(W + lane);
    float w1 = __ldg(W + lane + 32);
    float s = xr[lane] * w0 + xr[lane + 32] * w1;
    // warp reduce
    #pragma unroll
    for (int off = 16; off > 0; off >>= 1)
        s += __shfl_xor_sync(0xFFFFFFFFu, s, off);
    if (lane == 0) {
        g_y0[warp] = s;
        g_deg[warp] = 1.0f;   // self-loop
    }
}

// ---------------------------------------------------------------------------
// Kernel 2: degree accumulation at destination. 4 edges/thread via int4.
// ---------------------------------------------------------------------------
__global__ void k_deg(const int* __restrict__ col) {
    int t = blockIdx.x * blockDim.x + threadIdx.x;
    if (t >= N_EDGES / 4) return;
    int4 c = reinterpret_cast<const int4*>(col)[t];
    atomicAdd(&g_deg[c.x], 1.0f);
    atomicAdd(&g_deg[c.y], 1.0f);
    atomicAdd(&g_deg[c.z], 1.0f);
    atomicAdd(&g_deg[c.w], 1.0f);
}

// ---------------------------------------------------------------------------
// Kernel 3: dinv = rsqrt(deg) (deg >= 1 always), fused with hop-1 self-loop
// init: t1 = dinv^2 * y0.
// ---------------------------------------------------------------------------
__global__ void k_dinv_init1() {
    int i = blockIdx.x * blockDim.x + threadIdx.x;
    if (i >= N_NODES) return;
    float d = rsqrtf(g_deg[i]);
    g_dinv[i] = d;
    g_t1[i] = d * d * g_y0[i];
}

// ---------------------------------------------------------------------------
// Edge propagation: dst[col] += norm * src[row].
// FIRST pass computes norm = dinv[row]*dinv[col] and caches it.
// 4 edges/thread: int4 index loads, float4 norm load/store.
// ---------------------------------------------------------------------------
template <bool FIRST>
__global__ void k_edge(const int* __restrict__ row,
                       const int* __restrict__ col,
                       const float* __restrict__ src,
                       float* __restrict__ dst) {
    int t = blockIdx.x * blockDim.x + threadIdx.x;
    if (t >= N_EDGES / 4) return;
    int4 r = reinterpret_cast<const int4*>(row)[t];
    int4 c = reinterpret_cast<const int4*>(col)[t];
    float4 n;
    if (FIRST) {
        n.x = __ldg(&g_dinv[r.x]) * __ldg(&g_dinv[c.x]);
        n.y = __ldg(&g_dinv[r.y]) * __ldg(&g_dinv[c.y]);
        n.z = __ldg(&g_dinv[r.z]) * __ldg(&g_dinv[c.z]);
        n.w = __ldg(&g_dinv[r.w]) * __ldg(&g_dinv[c.w]);
        reinterpret_cast<float4*>(g_norm)[t] = n;
    } else {
        n = reinterpret_cast<const float4*>(g_norm)[t];
    }
    atomicAdd(&dst[c.x], n.x * __ldg(&src[r.x]));
    atomicAdd(&dst[c.y], n.y * __ldg(&src[r.y]));
    atomicAdd(&dst[c.z], n.z * __ldg(&src[r.z]));
    atomicAdd(&dst[c.w], n.w * __ldg(&src[r.w]));
}

// ---------------------------------------------------------------------------
// Self-loop init for hops 2/3: dst = dinv^2 * src (+ bias on the last hop,
// writing straight into d_out so the final edge pass accumulates on top).
// ---------------------------------------------------------------------------
__global__ void k_hop_init(const float* __restrict__ src,
                           float* __restrict__ dst,
                           const float* __restrict__ bias) {
    int i = blockIdx.x * blockDim.x + threadIdx.x;
    if (i >= N_NODES) return;
    float d = g_dinv[i];
    float v = d * d * src[i];
    if (bias) v += __ldg(bias);
    dst[i] = v;
}

extern "C" void kernel_launch(void* const* d_in, const int* in_sizes, int n_in,
                              void* d_out, int out_size) {
    const float* x  = (const float*)d_in[0];
    const int*   ei = (const int*)d_in[1];      // [2, N_EDGES]
    const float* W  = (const float*)d_in[2];    // [1, N_FEATS]
    const float* b  = (const float*)d_in[3];    // [1]
    float* out = (float*)d_out;                 // [N_NODES, 1]

    const int* row = ei;             // source (x_j gathered here)
    const int* col = ei + N_EDGES;   // destination (scatter target)

    float* t1p; cudaGetSymbolAddress((void**)&t1p, g_t1);
    float* t2p; cudaGetSymbolAddress((void**)&t2p, g_t2);
    float* y0p; cudaGetSymbolAddress((void**)&y0p, g_y0);

    const int TB = 256;
    int grid_nodes = (N_NODES + TB - 1) / TB;
    int grid_proj  = (N_NODES * 32 + TB - 1) / TB;   // warp per node
    int grid_edge4 = (N_EDGES / 4 + TB - 1) / TB;

    // 1) projection + deg self-loop init
    k_proj_init<<<grid_proj, TB>>>(x, W);
    // 2) degree
    k_deg<<<grid_edge4, TB>>>(col);
    // 3) dinv + hop1 self-loop init (t1 = dinv^2 * y0)
    k_dinv_init1<<<grid_nodes, TB>>>();
    // hop 1: t1 += norm * y0[row]   (computes+caches norm)
    k_edge<true><<<grid_edge4, TB>>>(row, col, y0p, t1p);
    // hop 2: t2 = dinv^2*t1 ; t2 += norm * t1[row]
    k_hop_init<<<grid_nodes, TB>>>(t1p, t2p, nullptr);
    k_edge<false><<<grid_edge4, TB>>>(row, col, t1p, t2p);
    // hop 3 (into d_out, with bias folded into init): out = dinv^2*t2 + b ; out += norm * t2[row]
    k_hop_init<<<grid_nodes, TB>>>(t2p, out, b);
    k_edge<false><<<grid_edge4, TB>>>(row, col, t2p, out);
}

// round 2
// speedup vs baseline: 1.0815x; 1.0815x over previous
#include <cuda_runtime.h>

#define N_NODES 50000
#define N_EDGES 800000
#define N_FEATS 64
#define NCHUNK  (N_EDGES / 2)

// Scratch (allocation-free): 4 x 200KB
__device__ float g_deg[N_NODES];
__device__ float g_a[N_NODES];
__device__ float g_b[N_NODES];
__device__ float g_c[N_NODES];

// ---------------------------------------------------------------------------
// Projection y0 = x[i,:] . w  (warp per node, coalesced 128B rows)
// + deg init (self-loop contributes 1).
// ---------------------------------------------------------------------------
__global__ void k_proj(const float* __restrict__ x,
                       const float* __restrict__ W) {
    int warp = (blockIdx.x * blockDim.x + threadIdx.x) >> 5;
    int lane = threadIdx.x & 31;
    if (warp >= N_NODES) return;
    const float* xr = x + (size_t)warp * N_FEATS;
    float s = xr[lane] * __ldg(W + lane) + xr[lane + 32] * __ldg(W + lane + 32);
    #pragma unroll
    for (int off = 16; off > 0; off >>= 1)
        s += __shfl_xor_sync(0xFFFFFFFFu, s, off);
    if (lane == 0) {
        g_a[warp]   = s;     // y0
        g_deg[warp] = 1.0f;  // self-loop
    }
}

// ---------------------------------------------------------------------------
// Degree at destination. 2 edges/thread, full-residency grid-stride.
// ---------------------------------------------------------------------------
__global__ void __launch_bounds__(256, 8)
k_deg(const int* __restrict__ col) {
    int stride = gridDim.x * blockDim.x;
    for (int t = blockIdx.x * blockDim.x + threadIdx.x; t < NCHUNK; t += stride) {
        int2 c = reinterpret_cast<const int2*>(col)[t];
        atomicAdd(&g_deg[c.x], 1.0f);
        atomicAdd(&g_deg[c.y], 1.0f);
    }
}

// ---------------------------------------------------------------------------
// u0 = rsqrt(deg) * y0 ; duplicate into gather-source (g_b) and
// accumulator (g_c) — the copy in the accumulator IS the self-loop term.
// ---------------------------------------------------------------------------
__global__ void k_scale2() {
    int i = blockIdx.x * blockDim.x + threadIdx.x;
    if (i >= N_NODES) return;
    float v = rsqrtf(g_deg[i]) * g_a[i];
    g_b[i] = v;
    g_c[i] = v;
}

// ---------------------------------------------------------------------------
// Edge pass: dst[col] += src[row]. No weights — normalization is factored
// into the node-phase kernels. Pure gather + RED.
// ---------------------------------------------------------------------------
__global__ void __launch_bounds__(256, 8)
k_edge(const int* __restrict__ row, const int* __restrict__ col,
       const float* __restrict__ src, float* __restrict__ dst) {
    int stride = gridDim.x * blockDim.x;
    for (int t = blockIdx.x * blockDim.x + threadIdx.x; t < NCHUNK; t += stride) {
        int2 r = reinterpret_cast<const int2*>(row)[t];
        int2 c = reinterpret_cast<const int2*>(col)[t];
        float vx = __ldg(src + r.x);
        float vy = __ldg(src + r.y);
        atomicAdd(dst + c.x, vx);
        atomicAdd(dst + c.y, vy);
    }
}

// ---------------------------------------------------------------------------
// Mid-hop: u' = s/deg ; duplicate into next gather-source and accumulator.
// ---------------------------------------------------------------------------
__global__ void k_div2(const float* __restrict__ s,
                       float* __restrict__ u, float* __restrict__ s2) {
    int i = blockIdx.x * blockDim.x + threadIdx.x;
    if (i >= N_NODES) return;
    float v = s[i] / g_deg[i];
    u[i]  = v;
    s2[i] = v;
}

// ---------------------------------------------------------------------------
// Final: out = rsqrt(deg) * s3 + b (in place on d_out).
// ---------------------------------------------------------------------------
__global__ void k_final(float* __restrict__ out, const float* __restrict__ b) {
    int i = blockIdx.x * blockDim.x + threadIdx.x;
    if (i >= N_NODES) return;
    out[i] = rsqrtf(g_deg[i]) * out[i] + __ldg(b);
}

extern "C" void kernel_launch(void* const* d_in, const int* in_sizes, int n_in,
                              void* d_out, int out_size) {
    const float* x  = (const float*)d_in[0];
    const int*   ei = (const int*)d_in[1];   // [2, N_EDGES]
    const float* W  = (const float*)d_in[2]; // [1, N_FEATS]
    const float* b  = (const float*)d_in[3]; // [1]
    float* out = (float*)d_out;              // [N_NODES, 1]

    const int* row = ei;            // gather source
    const int* col = ei + N_EDGES;  // scatter destination

    float* ap; cudaGetSymbolAddress((void**)&ap, g_a);
    float* bp; cudaGetSymbolAddress((void**)&bp, g_b);
    float* cp; cudaGetSymbolAddress((void**)&cp, g_c);

    const int TB = 256;
    int grid_nodes = (N_NODES + TB - 1) / TB;
    int grid_proj  = (N_NODES * 32 + TB - 1) / TB;
    int grid_edge  = 148 * 8;  // full residency at 256 thr/block

    k_proj<<<grid_proj, TB>>>(x, W);
    k_deg<<<grid_edge, TB>>>(col);

    // hop 1: u0 = rsqrt(deg)*y0 -> (g_b src, g_c acc); acc += gather
    k_scale2<<<grid_nodes, TB>>>();
    k_edge<<<grid_edge, TB>>>(row, col, bp, cp);

    // hop 2: u1 = s1/deg -> (g_a src, g_b acc)
    k_div2<<<grid_nodes, TB>>>(cp, ap, bp);
    k_edge<<<grid_edge, TB>>>(row, col, ap, bp);

    // hop 3: u2 = s2/deg -> (g_c src, out acc)
    k_div2<<<grid_nodes, TB>>>(bp, cp, out);
    k_edge<<<grid_edge, TB>>>(row, col, cp, out);

    // out = rsqrt(deg)*s3 + b
    k_final<<<grid_nodes, TB>>>(out, b);
}